// round 14
// baseline (speedup 1.0000x reference)
#include <cuda_runtime.h>
#include <cuda_fp16.h>
#include <cstdint>
#include <math.h>

// ---------------------------------------------------------------------------
// Problem constants
// ---------------------------------------------------------------------------
#define BATCH   16384
#define KDIM    512          // I == H == 512 (GEMM K)
#define FOURH   2048
#define HD      512          // hidden dim
#define LN_EPS  1e-5f

// Scratch (device globals: allocation-guard-safe)
__device__ __half g_wi[(size_t)BATCH * FOURH];    // x  @ w_ih  (fp16)
__device__ __half g_wh[(size_t)BATCH * FOURH];    // h0 @ w_hh  (fp16)
__device__ __half g_x16[(size_t)BATCH * KDIM];
__device__ __half g_h16[(size_t)BATCH * KDIM];
__device__ __half g_wih16[(size_t)FOURH * KDIM];  // K-major [4H, K]
__device__ __half g_whh16[(size_t)FOURH * KDIM];

// ---------------------------------------------------------------------------
// Fused fp32 -> fp16 convert for x and h0 (blockIdx.y selects source)
// ---------------------------------------------------------------------------
__global__ void cvt16_dual_kernel(const float* __restrict__ x,
                                  const float* __restrict__ h0,
                                  __half* __restrict__ xd,
                                  __half* __restrict__ hd, size_t n4)
{
    const size_t i = (size_t)blockIdx.x * blockDim.x + threadIdx.x;
    if (i >= n4) return;
    const float* src = blockIdx.y ? h0 : x;
    __half*      dst = blockIdx.y ? hd : xd;
    const float4 v = ((const float4*)src)[i];
    ((__half2*)dst)[i * 2]     = __floats2half2_rn(v.x, v.y);
    ((__half2*)dst)[i * 2 + 1] = __floats2half2_rn(v.z, v.w);
}

// ---------------------------------------------------------------------------
// Fused weight transpose+convert: W[K, 4H] fp32 -> WT[4H, K] fp16
// blockIdx.z selects w_ih / w_hh.
// ---------------------------------------------------------------------------
__global__ void transpose16_dual_kernel(const float* __restrict__ Wih,
                                        const float* __restrict__ Whh,
                                        __half* __restrict__ WTih,
                                        __half* __restrict__ WThh)
{
    __shared__ float t[32][33];
    const float* W  = blockIdx.z ? Whh : Wih;
    __half*      WT = blockIdx.z ? WThh : WTih;
    const int bx = blockIdx.x * 32;   // col in W  (n)
    const int by = blockIdx.y * 32;   // row in W  (k)
    const int tx = threadIdx.x, ty = threadIdx.y;
#pragma unroll
    for (int i = 0; i < 32; i += 8)
        t[ty + i][tx] = W[(size_t)(by + ty + i) * FOURH + bx + tx];
    __syncthreads();
#pragma unroll
    for (int i = 0; i < 32; i += 8)
        WT[(size_t)(bx + ty + i) * KDIM + by + tx] = __float2half_rn(t[tx][ty + i]);
}

// ---------------------------------------------------------------------------
// mma.sync fp16 GEMM (single-pass, f32 accumulate, fp16 output) — validated.
// ---------------------------------------------------------------------------
#define BM      128
#define BN      128
#define BKE     64
#define STAGES  3
#define NKIT    (KDIM / BKE)             // 8
#define TILE_B  (128 * 128)              // 16 KB per operand tile
#define A_OFF   0
#define B_OFF   (TILE_B)
#define STAGE_BYTES (2 * TILE_B)         // 32 KB
#define SMEM_DYN (STAGES * STAGE_BYTES + 1024)   // ~97 KB -> 2 CTAs/SM

__device__ __forceinline__ uint32_t cvta_smem(const void* p) {
    return (uint32_t)__cvta_generic_to_shared(p);
}
__device__ __forceinline__ void cp16(uint32_t dst, const void* src) {
    asm volatile("cp.async.cg.shared.global [%0], [%1], 16;" :: "r"(dst), "l"(src));
}
__device__ __forceinline__ void cp_commit() {
    asm volatile("cp.async.commit_group;" ::: "memory");
}
template <int N>
__device__ __forceinline__ void cp_wait() {
    asm volatile("cp.async.wait_group %0;" :: "n"(N) : "memory");
}
__device__ __forceinline__ void ldsm4(uint32_t& r0, uint32_t& r1,
                                      uint32_t& r2, uint32_t& r3, uint32_t addr) {
    asm volatile("ldmatrix.sync.aligned.m8n8.x4.shared.b16 {%0,%1,%2,%3}, [%4];"
                 : "=r"(r0), "=r"(r1), "=r"(r2), "=r"(r3) : "r"(addr));
}
__device__ __forceinline__ void mma16816(float* d, const uint32_t* a,
                                         const uint32_t* b) {
    asm volatile(
        "mma.sync.aligned.m16n8k16.row.col.f32.f16.f16.f32 "
        "{%0,%1,%2,%3}, {%4,%5,%6,%7}, {%8,%9}, {%0,%1,%2,%3};"
        : "+f"(d[0]), "+f"(d[1]), "+f"(d[2]), "+f"(d[3])
        : "r"(a[0]), "r"(a[1]), "r"(a[2]), "r"(a[3]), "r"(b[0]), "r"(b[1]));
}

__global__ void __launch_bounds__(256, 2)
gemm_f16_kernel(const __half* __restrict__ A0, const __half* __restrict__ A1,
                const __half* __restrict__ B0, const __half* __restrict__ B1,
                __half* __restrict__ C0, __half* __restrict__ C1)
{
    extern __shared__ char dsmem_raw[];

    const int tid = threadIdx.x;
    const int wid = tid >> 5;
    const int lid = tid & 31;

    const __half* A = blockIdx.z ? A1 : A0;
    const __half* B = blockIdx.z ? B1 : B0;
    __half*       C = blockIdx.z ? C1 : C0;

    const int brow = blockIdx.y * BM;
    const int bcol = blockIdx.x * BN;

    uint32_t sbase = cvta_smem(dsmem_raw);
    sbase = (sbase + 127u) & ~127u;

    const int wm = (wid & 1) * 64;
    const int wn = (wid >> 1) * 32;

    const int lq = lid >> 3;
    const int lr = lid & 7;
    const int a_row = lr + ((lq & 1) ? 8 : 0);
    const int a_kbh = lq >> 1;
    const int b_row = lr + ((lq >> 1) ? 8 : 0);
    const int b_kbh = lq & 1;

    float acc[4][4][4];
#pragma unroll
    for (int mt = 0; mt < 4; ++mt)
#pragma unroll
        for (int nt = 0; nt < 4; ++nt)
#pragma unroll
            for (int r = 0; r < 4; ++r) acc[mt][nt][r] = 0.0f;

    auto load_stage = [&](int s, int kc) {
        const int k0 = kc * BKE;
        const uint32_t sb = sbase + s * STAGE_BYTES;
#pragma unroll
        for (int i = 0; i < 4; ++i) {
            const int idx = tid + 256 * i;
            const int row = idx >> 3, ch = idx & 7;
            const uint32_t off = (uint32_t)(row * 128 + ((ch ^ (row & 7)) * 16));
            const size_t ga = (size_t)(brow + row) * KDIM + k0 + ch * 8;
            const size_t gb = (size_t)(bcol + row) * KDIM + k0 + ch * 8;
            cp16(sb + A_OFF + off, A + ga);
            cp16(sb + B_OFF + off, B + gb);
        }
        cp_commit();
    };

    load_stage(0, 0);
    load_stage(1, 1);

#pragma unroll 1
    for (int kc = 0; kc < NKIT; ++kc) {
        const int s = kc % STAGES;
        if (kc + 2 < NKIT) load_stage((kc + 2) % STAGES, kc + 2);
        else               cp_commit();
        cp_wait<2>();
        __syncthreads();

        const uint32_t ab = sbase + s * STAGE_BYTES + A_OFF;
        const uint32_t bb = sbase + s * STAGE_BYTES + B_OFF;

#pragma unroll
        for (int ks = 0; ks < 4; ++ks) {
            uint32_t a[4][4], b[8];
#pragma unroll
            for (int mt = 0; mt < 4; ++mt) {
                const int row = wm + mt * 16 + a_row;
                const int ch  = ks * 2 + a_kbh;
                const uint32_t off =
                    (uint32_t)(row * 128 + ((ch ^ (row & 7)) * 16));
                ldsm4(a[mt][0], a[mt][1], a[mt][2], a[mt][3], ab + off);
            }
#pragma unroll
            for (int np = 0; np < 2; ++np) {
                const int row = wn + np * 16 + b_row;
                const int ch  = ks * 2 + b_kbh;
                const uint32_t off =
                    (uint32_t)(row * 128 + ((ch ^ (row & 7)) * 16));
                ldsm4(b[np*4], b[np*4+1], b[np*4+2], b[np*4+3], bb + off);
            }
#pragma unroll
            for (int mt = 0; mt < 4; ++mt)
#pragma unroll
                for (int nt = 0; nt < 4; ++nt) {
                    const int bi = (nt >> 1) * 4 + (nt & 1) * 2;
                    mma16816(acc[mt][nt], a[mt], &b[bi]);
                }
        }
        __syncthreads();
    }

    const int er = lid >> 2;
    const int ec = (lid & 3) * 2;
#pragma unroll
    for (int mt = 0; mt < 4; ++mt) {
#pragma unroll
        for (int nt = 0; nt < 4; ++nt) {
            const int r0 = brow + wm + mt * 16 + er;
            const int cc = bcol + wn + nt * 8 + ec;
            *(__half2*)&C[(size_t)r0 * FOURH + cc] =
                __floats2half2_rn(acc[mt][nt][0], acc[mt][nt][1]);
            *(__half2*)&C[(size_t)(r0 + 8) * FOURH + cc] =
                __floats2half2_rn(acc[mt][nt][2], acc[mt][nt][3]);
        }
    }
}

// ---------------------------------------------------------------------------
// LSTM epilogue v3: warp-per-row, zero barriers, SMEM-staged intermediates.
//   c1 and o-gate pre-activations live in a warp-private SMEM slice instead
//   of registers (R13's 169-reg / 11% occ failure mode).
// Block = 8 warps = 8 rows; 32 KB smem/block; grid = BATCH/8.
// ---------------------------------------------------------------------------
__device__ __forceinline__ float sigmoidf_(float v) {
    return 1.0f / (1.0f + expf(-v));
}

__global__ __launch_bounds__(256)
void lstm_ln_kernel(const float* __restrict__ c0,
                    const float* __restrict__ bias_x,
                    const float* __restrict__ bias_h,
                    const float* __restrict__ g_ih,
                    const float* __restrict__ b_ih,
                    const float* __restrict__ g_hh,
                    const float* __restrict__ b_hh,
                    const float* __restrict__ g_c,
                    const float* __restrict__ b_c,
                    float* __restrict__ out)
{
    __shared__ float sm_c1[8][HD];   // 16 KB
    __shared__ float sm_o[8][HD];    // 16 KB

    const int warp = threadIdx.x >> 5;
    const int lane = threadIdx.x & 31;
    const int b = blockIdx.x * 8 + warp;

    const __half2* wh2 = (const __half2*)g_wh + (size_t)b * (FOURH / 2);
    const __half2* wi2 = (const __half2*)g_wi + (size_t)b * (FOURH / 2);

    // ---- Pass 1: dual LN statistics over 4H (warp shuffles only) ----
    float s_h = 0.f, ss_h = 0.f, s_i = 0.f, ss_i = 0.f;
#pragma unroll
    for (int m = 0; m < 32; ++m) {
        const int p = lane + 32 * m;
        float2 a = __half22float2(wh2[p]);
        float2 c = __half22float2(wi2[p]);
        const float2 bh = *(const float2*)&bias_h[2 * p];
        const float2 bx = *(const float2*)&bias_x[2 * p];
        a.x += bh.x; a.y += bh.y;
        c.x += bx.x; c.y += bx.y;
        s_h += a.x + a.y; ss_h += a.x * a.x + a.y * a.y;
        s_i += c.x + c.y; ss_i += c.x * c.x + c.y * c.y;
    }
#pragma unroll
    for (int off = 16; off > 0; off >>= 1) {
        s_h  += __shfl_xor_sync(0xffffffffu, s_h,  off);
        ss_h += __shfl_xor_sync(0xffffffffu, ss_h, off);
        s_i  += __shfl_xor_sync(0xffffffffu, s_i,  off);
        ss_i += __shfl_xor_sync(0xffffffffu, ss_i, off);
    }
    const float inv4h  = 1.0f / (float)FOURH;
    const float mean_h = s_h * inv4h;
    const float var_h  = ss_h * inv4h - mean_h * mean_h;
    const float rstd_h = rsqrtf(var_h + LN_EPS);
    const float mean_i = s_i * inv4h;
    const float var_i  = ss_i * inv4h - mean_i * mean_i;
    const float rstd_i = rsqrtf(var_i + LN_EPS);

    // ---- Pass 2: gates (row re-read is L1-hot); c1/o staged to SMEM ----
    float sc = 0.f, ssc = 0.f;
#pragma unroll
    for (int m = 0; m < 8; ++m) {
        const int q = lane + 32 * m;     // half2-pair -> hidden units 2q, 2q+1
        float2 sg[4];
#pragma unroll
        for (int gi = 0; gi < 4; ++gi) {
            const int p = gi * 256 + q;
            const int j = 2 * p;
            const float2 a  = __half22float2(wh2[p]);
            const float2 c  = __half22float2(wi2[p]);
            const float2 bh = *(const float2*)&bias_h[j];
            const float2 bx = *(const float2*)&bias_x[j];
            const float2 gh = *(const float2*)&g_hh[j];
            const float2 bhh= *(const float2*)&b_hh[j];
            const float2 gih= *(const float2*)&g_ih[j];
            const float2 bih= *(const float2*)&b_ih[j];
            sg[gi].x = (a.x + bh.x - mean_h) * rstd_h * gh.x + bhh.x
                     + (c.x + bx.x - mean_i) * rstd_i * gih.x + bih.x;
            sg[gi].y = (a.y + bh.y - mean_h) * rstd_h * gh.y + bhh.y
                     + (c.y + bx.y - mean_i) * rstd_i * gih.y + bih.y;
        }
        const float2 c0v = *(const float2*)&c0[(size_t)b * HD + 2 * q];
        // sg[0]=f, sg[1]=i, sg[2]=o, sg[3]=g
        const float c1x = sigmoidf_(sg[0].x) * c0v.x + sigmoidf_(sg[1].x) * tanhf(sg[3].x);
        const float c1y = sigmoidf_(sg[0].y) * c0v.y + sigmoidf_(sg[1].y) * tanhf(sg[3].y);
        *(float2*)&sm_c1[warp][2 * q] = make_float2(c1x, c1y);
        *(float2*)&sm_o[warp][2 * q]  = sg[2];
        sc  += c1x + c1y;
        ssc += c1x * c1x + c1y * c1y;
    }

    // ---- c1 LayerNorm (warp-level; warp-private smem, no barrier) ----
#pragma unroll
    for (int off = 16; off > 0; off >>= 1) {
        sc  += __shfl_xor_sync(0xffffffffu, sc,  off);
        ssc += __shfl_xor_sync(0xffffffffu, ssc, off);
    }
    const float invh   = 1.0f / (float)HD;
    const float mean_c = sc * invh;
    const float var_c  = ssc * invh - mean_c * mean_c;
    const float rstd_c = rsqrtf(var_c + LN_EPS);

    float* out_h1 = out + (size_t)b * HD;
    float* out_c1 = out + (size_t)BATCH * HD + (size_t)b * HD;
#pragma unroll
    for (int m = 0; m < 8; ++m) {
        const int q = lane + 32 * m;
        const float2 c1v = *(const float2*)&sm_c1[warp][2 * q];
        const float2 ov  = *(const float2*)&sm_o[warp][2 * q];
        const float2 gc  = *(const float2*)&g_c[2 * q];
        const float2 bc  = *(const float2*)&b_c[2 * q];
        const float lc0 = (c1v.x - mean_c) * rstd_c * gc.x + bc.x;
        const float lc1 = (c1v.y - mean_c) * rstd_c * gc.y + bc.y;
        *(float2*)&out_h1[2 * q] =
            make_float2(sigmoidf_(ov.x) * tanhf(lc0),
                        sigmoidf_(ov.y) * tanhf(lc1));
        *(float2*)&out_c1[2 * q] = c1v;
    }
}

// ---------------------------------------------------------------------------
// Launch
// ---------------------------------------------------------------------------
extern "C" void kernel_launch(void* const* d_in, const int* in_sizes, int n_in,
                              void* d_out, int out_size)
{
    const float* x      = (const float*)d_in[0];
    const float* h0     = (const float*)d_in[1];
    const float* c0     = (const float*)d_in[2];
    const float* w_ih   = (const float*)d_in[3];
    const float* w_hh   = (const float*)d_in[4];
    const float* bias_x = (const float*)d_in[5];
    const float* bias_h = (const float*)d_in[6];
    const float* g_ih   = (const float*)d_in[7];
    const float* b_ih   = (const float*)d_in[8];
    const float* g_hh   = (const float*)d_in[9];
    const float* b_hh   = (const float*)d_in[10];
    const float* g_c    = (const float*)d_in[11];
    const float* b_c    = (const float*)d_in[12];
    float* out = (float*)d_out;

    __half *wi_ptr, *wh_ptr, *x16, *h16, *wih16, *whh16;
    cudaGetSymbolAddress((void**)&wi_ptr, g_wi);
    cudaGetSymbolAddress((void**)&wh_ptr, g_wh);
    cudaGetSymbolAddress((void**)&x16,   g_x16);
    cudaGetSymbolAddress((void**)&h16,   g_h16);
    cudaGetSymbolAddress((void**)&wih16, g_wih16);
    cudaGetSymbolAddress((void**)&whh16, g_whh16);

    cudaFuncSetAttribute(gemm_f16_kernel,
                         cudaFuncAttributeMaxDynamicSharedMemorySize, SMEM_DYN);

    // Fused activation conversions (x, h0) in one launch
    const size_t n4 = (size_t)BATCH * KDIM / 4;
    dim3 cg((unsigned)((n4 + 255) / 256), 2);
    cvt16_dual_kernel<<<cg, 256>>>(x, h0, x16, h16, n4);

    // Fused weight transposes in one launch
    dim3 tb(32, 8);
    dim3 tg(FOURH / 32, KDIM / 32, 2);
    transpose16_dual_kernel<<<tg, tb>>>(w_ih, w_hh, wih16, whh16);

    // Both GEMMs in one launch: z=0 -> wi (x @ w_ih), z=1 -> wh (h0 @ w_hh)
    dim3 gg(FOURH / BN, BATCH / BM, 2);     // (16, 128, 2)
    gemm_f16_kernel<<<gg, 256, SMEM_DYN>>>(x16, h16, wih16, whh16,
                                           wi_ptr, wh_ptr);

    // Epilogue: warp-per-row, SMEM-staged, 2048 blocks
    lstm_ln_kernel<<<BATCH / 8, 256>>>(c0, bias_x, bias_h, g_ih, b_ih,
                                       g_hh, b_hh, g_c, b_c, out);
}

// round 15
// speedup vs baseline: 1.2203x; 1.2203x over previous
#include <cuda_runtime.h>
#include <cuda_fp16.h>
#include <cstdint>
#include <math.h>

// ---------------------------------------------------------------------------
// Problem constants
// ---------------------------------------------------------------------------
#define BATCH   16384
#define KDIM    512          // I == H == 512 (GEMM K)
#define FOURH   2048
#define HD      512
#define LN_EPS  1e-5f

// Scratch (device globals: allocation-guard-safe)
__device__ __half g_wi[(size_t)BATCH * FOURH];    // x  @ w_ih  (fp16)
__device__ __half g_wh[(size_t)BATCH * FOURH];    // h0 @ w_hh  (fp16)
__device__ __half g_x16[(size_t)BATCH * KDIM];
__device__ __half g_h16[(size_t)BATCH * KDIM];
__device__ __half g_wih16[(size_t)FOURH * KDIM];  // K-major [4H, K]
__device__ __half g_whh16[(size_t)FOURH * KDIM];

// ---------------------------------------------------------------------------
// Fused fp32 -> fp16 convert for x and h0 (blockIdx.y selects source)
// ---------------------------------------------------------------------------
__global__ void cvt16_dual_kernel(const float* __restrict__ x,
                                  const float* __restrict__ h0,
                                  __half* __restrict__ xd,
                                  __half* __restrict__ hd, size_t n4)
{
    const size_t i = (size_t)blockIdx.x * blockDim.x + threadIdx.x;
    if (i >= n4) return;
    const float* src = blockIdx.y ? h0 : x;
    __half*      dst = blockIdx.y ? hd : xd;
    const float4 v = ((const float4*)src)[i];
    ((__half2*)dst)[i * 2]     = __floats2half2_rn(v.x, v.y);
    ((__half2*)dst)[i * 2 + 1] = __floats2half2_rn(v.z, v.w);
}

// ---------------------------------------------------------------------------
// Fused weight transpose+convert: W[K, 4H] fp32 -> WT[4H, K] fp16
// blockIdx.z selects w_ih / w_hh.
// ---------------------------------------------------------------------------
__global__ void transpose16_dual_kernel(const float* __restrict__ Wih,
                                        const float* __restrict__ Whh,
                                        __half* __restrict__ WTih,
                                        __half* __restrict__ WThh)
{
    __shared__ float t[32][33];
    const float* W  = blockIdx.z ? Whh : Wih;
    __half*      WT = blockIdx.z ? WThh : WTih;
    const int bx = blockIdx.x * 32;   // col in W  (n)
    const int by = blockIdx.y * 32;   // row in W  (k)
    const int tx = threadIdx.x, ty = threadIdx.y;
#pragma unroll
    for (int i = 0; i < 32; i += 8)
        t[ty + i][tx] = W[(size_t)(by + ty + i) * FOURH + bx + tx];
    __syncthreads();
#pragma unroll
    for (int i = 0; i < 32; i += 8)
        WT[(size_t)(bx + ty + i) * KDIM + by + tx] = __float2half_rn(t[tx][ty + i]);
}

// ---------------------------------------------------------------------------
// mma.sync fp16 GEMM (single-pass, f32 accumulate, fp16 output) — validated.
// ---------------------------------------------------------------------------
#define BM      128
#define BN      128
#define BKE     64
#define STAGES  3
#define NKIT    (KDIM / BKE)             // 8
#define TILE_B  (128 * 128)              // 16 KB per operand tile
#define A_OFF   0
#define B_OFF   (TILE_B)
#define STAGE_BYTES (2 * TILE_B)         // 32 KB
#define SMEM_DYN (STAGES * STAGE_BYTES + 1024)   // ~97 KB -> 2 CTAs/SM

__device__ __forceinline__ uint32_t cvta_smem(const void* p) {
    return (uint32_t)__cvta_generic_to_shared(p);
}
__device__ __forceinline__ void cp16(uint32_t dst, const void* src) {
    asm volatile("cp.async.cg.shared.global [%0], [%1], 16;" :: "r"(dst), "l"(src));
}
__device__ __forceinline__ void cp_commit() {
    asm volatile("cp.async.commit_group;" ::: "memory");
}
template <int N>
__device__ __forceinline__ void cp_wait() {
    asm volatile("cp.async.wait_group %0;" :: "n"(N) : "memory");
}
__device__ __forceinline__ void ldsm4(uint32_t& r0, uint32_t& r1,
                                      uint32_t& r2, uint32_t& r3, uint32_t addr) {
    asm volatile("ldmatrix.sync.aligned.m8n8.x4.shared.b16 {%0,%1,%2,%3}, [%4];"
                 : "=r"(r0), "=r"(r1), "=r"(r2), "=r"(r3) : "r"(addr));
}
__device__ __forceinline__ void mma16816(float* d, const uint32_t* a,
                                         const uint32_t* b) {
    asm volatile(
        "mma.sync.aligned.m16n8k16.row.col.f32.f16.f16.f32 "
        "{%0,%1,%2,%3}, {%4,%5,%6,%7}, {%8,%9}, {%0,%1,%2,%3};"
        : "+f"(d[0]), "+f"(d[1]), "+f"(d[2]), "+f"(d[3])
        : "r"(a[0]), "r"(a[1]), "r"(a[2]), "r"(a[3]), "r"(b[0]), "r"(b[1]));
}

__global__ void __launch_bounds__(256, 2)
gemm_f16_kernel(const __half* __restrict__ A0, const __half* __restrict__ A1,
                const __half* __restrict__ B0, const __half* __restrict__ B1,
                __half* __restrict__ C0, __half* __restrict__ C1)
{
    extern __shared__ char dsmem_raw[];

    const int tid = threadIdx.x;
    const int wid = tid >> 5;
    const int lid = tid & 31;

    const __half* A = blockIdx.z ? A1 : A0;
    const __half* B = blockIdx.z ? B1 : B0;
    __half*       C = blockIdx.z ? C1 : C0;

    const int brow = blockIdx.y * BM;
    const int bcol = blockIdx.x * BN;

    uint32_t sbase = cvta_smem(dsmem_raw);
    sbase = (sbase + 127u) & ~127u;

    const int wm = (wid & 1) * 64;
    const int wn = (wid >> 1) * 32;

    const int lq = lid >> 3;
    const int lr = lid & 7;
    const int a_row = lr + ((lq & 1) ? 8 : 0);
    const int a_kbh = lq >> 1;
    const int b_row = lr + ((lq >> 1) ? 8 : 0);
    const int b_kbh = lq & 1;

    float acc[4][4][4];
#pragma unroll
    for (int mt = 0; mt < 4; ++mt)
#pragma unroll
        for (int nt = 0; nt < 4; ++nt)
#pragma unroll
            for (int r = 0; r < 4; ++r) acc[mt][nt][r] = 0.0f;

    auto load_stage = [&](int s, int kc) {
        const int k0 = kc * BKE;
        const uint32_t sb = sbase + s * STAGE_BYTES;
#pragma unroll
        for (int i = 0; i < 4; ++i) {
            const int idx = tid + 256 * i;
            const int row = idx >> 3, ch = idx & 7;
            const uint32_t off = (uint32_t)(row * 128 + ((ch ^ (row & 7)) * 16));
            const size_t ga = (size_t)(brow + row) * KDIM + k0 + ch * 8;
            const size_t gb = (size_t)(bcol + row) * KDIM + k0 + ch * 8;
            cp16(sb + A_OFF + off, A + ga);
            cp16(sb + B_OFF + off, B + gb);
        }
        cp_commit();
    };

    load_stage(0, 0);
    load_stage(1, 1);

#pragma unroll 1
    for (int kc = 0; kc < NKIT; ++kc) {
        const int s = kc % STAGES;
        if (kc + 2 < NKIT) load_stage((kc + 2) % STAGES, kc + 2);
        else               cp_commit();
        cp_wait<2>();
        __syncthreads();

        const uint32_t ab = sbase + s * STAGE_BYTES + A_OFF;
        const uint32_t bb = sbase + s * STAGE_BYTES + B_OFF;

#pragma unroll
        for (int ks = 0; ks < 4; ++ks) {
            uint32_t a[4][4], b[8];
#pragma unroll
            for (int mt = 0; mt < 4; ++mt) {
                const int row = wm + mt * 16 + a_row;
                const int ch  = ks * 2 + a_kbh;
                const uint32_t off =
                    (uint32_t)(row * 128 + ((ch ^ (row & 7)) * 16));
                ldsm4(a[mt][0], a[mt][1], a[mt][2], a[mt][3], ab + off);
            }
#pragma unroll
            for (int np = 0; np < 2; ++np) {
                const int row = wn + np * 16 + b_row;
                const int ch  = ks * 2 + b_kbh;
                const uint32_t off =
                    (uint32_t)(row * 128 + ((ch ^ (row & 7)) * 16));
                ldsm4(b[np*4], b[np*4+1], b[np*4+2], b[np*4+3], bb + off);
            }
#pragma unroll
            for (int mt = 0; mt < 4; ++mt)
#pragma unroll
                for (int nt = 0; nt < 4; ++nt) {
                    const int bi = (nt >> 1) * 4 + (nt & 1) * 2;
                    mma16816(acc[mt][nt], a[mt], &b[bi]);
                }
        }
        __syncthreads();
    }

    const int er = lid >> 2;
    const int ec = (lid & 3) * 2;
#pragma unroll
    for (int mt = 0; mt < 4; ++mt) {
#pragma unroll
        for (int nt = 0; nt < 4; ++nt) {
            const int r0 = brow + wm + mt * 16 + er;
            const int cc = bcol + wn + nt * 8 + ec;
            *(__half2*)&C[(size_t)r0 * FOURH + cc] =
                __floats2half2_rn(acc[mt][nt][0], acc[mt][nt][1]);
            *(__half2*)&C[(size_t)(r0 + 8) * FOURH + cc] =
                __floats2half2_rn(acc[mt][nt][2], acc[mt][nt][3]);
        }
    }
}

// ---------------------------------------------------------------------------
// LSTM epilogue — R12's validated block-per-row, half2-vectorized version
// (best measured epilogue; warp-per-row variants regressed in R13/R14).
// Block = 256 threads handles one row; thread t owns hidden units 2t, 2t+1.
// ---------------------------------------------------------------------------
__device__ __forceinline__ float sigmoidf_(float v) {
    return 1.0f / (1.0f + expf(-v));
}

__global__ __launch_bounds__(256)
void lstm_ln_kernel(const float* __restrict__ c0,
                    const float* __restrict__ bias_x,
                    const float* __restrict__ bias_h,
                    const float* __restrict__ g_ih,
                    const float* __restrict__ b_ih,
                    const float* __restrict__ g_hh,
                    const float* __restrict__ b_hh,
                    const float* __restrict__ g_c,
                    const float* __restrict__ b_c,
                    float* __restrict__ out)
{
    const int b = blockIdx.x;
    const int t = threadIdx.x;
    const int lane = t & 31;
    const int warp = t >> 5;

    const __half2* wh2 = (const __half2*)g_wh + (size_t)b * (FOURH / 2);
    const __half2* wi2 = (const __half2*)g_wi + (size_t)b * (FOURH / 2);

    __shared__ float red[32];

    // r indexes the gate (f=0, i=1, o=2, g=3); pair p = t + 256*r covers
    // elements 2p, 2p+1 = gate r, hidden units 2t, 2t+1.
    float2 vh[4], vi[4];
    float s_h = 0.f, ss_h = 0.f, s_i = 0.f, ss_i = 0.f;
#pragma unroll
    for (int r = 0; r < 4; ++r) {
        const int p = t + 256 * r;
        const int j = p * 2;
        float2 a = __half22float2(wh2[p]);
        float2 c = __half22float2(wi2[p]);
        const float2 bh = *(const float2*)&bias_h[j];
        const float2 bx = *(const float2*)&bias_x[j];
        a.x += bh.x; a.y += bh.y;
        c.x += bx.x; c.y += bx.y;
        vh[r] = a; vi[r] = c;
        s_h += a.x + a.y; ss_h += a.x * a.x + a.y * a.y;
        s_i += c.x + c.y; ss_i += c.x * c.x + c.y * c.y;
    }

#pragma unroll
    for (int off = 16; off > 0; off >>= 1) {
        s_h  += __shfl_xor_sync(0xffffffffu, s_h,  off);
        ss_h += __shfl_xor_sync(0xffffffffu, ss_h, off);
        s_i  += __shfl_xor_sync(0xffffffffu, s_i,  off);
        ss_i += __shfl_xor_sync(0xffffffffu, ss_i, off);
    }
    if (lane == 0) {
        red[warp]      = s_h;
        red[8 + warp]  = ss_h;
        red[16 + warp] = s_i;
        red[24 + warp] = ss_i;
    }
    __syncthreads();
    float S_h = 0.f, SS_h = 0.f, S_i = 0.f, SS_i = 0.f;
#pragma unroll
    for (int w = 0; w < 8; ++w) {
        S_h  += red[w];
        SS_h += red[8 + w];
        S_i  += red[16 + w];
        SS_i += red[24 + w];
    }

    const float inv4h  = 1.0f / (float)FOURH;
    const float mean_h = S_h * inv4h;
    const float var_h  = SS_h * inv4h - mean_h * mean_h;
    const float rstd_h = rsqrtf(var_h + LN_EPS);
    const float mean_i = S_i * inv4h;
    const float var_i  = SS_i * inv4h - mean_i * mean_i;
    const float rstd_i = rsqrtf(var_i + LN_EPS);

    float2 s[4];
#pragma unroll
    for (int r = 0; r < 4; ++r) {
        const int j = (t + 256 * r) * 2;
        const float2 gh = *(const float2*)&g_hh[j];
        const float2 bh = *(const float2*)&b_hh[j];
        const float2 gi = *(const float2*)&g_ih[j];
        const float2 bi = *(const float2*)&b_ih[j];
        s[r].x = (vh[r].x - mean_h) * rstd_h * gh.x + bh.x
               + (vi[r].x - mean_i) * rstd_i * gi.x + bi.x;
        s[r].y = (vh[r].y - mean_h) * rstd_h * gh.y + bh.y
               + (vi[r].y - mean_i) * rstd_i * gi.y + bi.y;
    }

    const float2 c0v = *(const float2*)&c0[(size_t)b * HD + 2 * t];

    // s[0]=f, s[1]=i, s[2]=o, s[3]=g  for hidden units 2t (.x), 2t+1 (.y)
    const float c1_0 = sigmoidf_(s[0].x) * c0v.x + sigmoidf_(s[1].x) * tanhf(s[3].x);
    const float c1_1 = sigmoidf_(s[0].y) * c0v.y + sigmoidf_(s[1].y) * tanhf(s[3].y);

    float sc  = c1_0 + c1_1;
    float ssc = c1_0 * c1_0 + c1_1 * c1_1;
#pragma unroll
    for (int off = 16; off > 0; off >>= 1) {
        sc  += __shfl_xor_sync(0xffffffffu, sc,  off);
        ssc += __shfl_xor_sync(0xffffffffu, ssc, off);
    }
    __syncthreads();   // protect red[] reuse
    if (lane == 0) {
        red[warp]     = sc;
        red[8 + warp] = ssc;
    }
    __syncthreads();
    float Sc = 0.f, SSc = 0.f;
#pragma unroll
    for (int w = 0; w < 8; ++w) { Sc += red[w]; SSc += red[8 + w]; }

    const float invh   = 1.0f / (float)HD;
    const float mean_c = Sc * invh;
    const float var_c  = SSc * invh - mean_c * mean_c;
    const float rstd_c = rsqrtf(var_c + LN_EPS);

    const float2 gc = *(const float2*)&g_c[2 * t];
    const float2 bc = *(const float2*)&b_c[2 * t];
    const float lc0 = (c1_0 - mean_c) * rstd_c * gc.x + bc.x;
    const float lc1 = (c1_1 - mean_c) * rstd_c * gc.y + bc.y;

    const float h1_0 = sigmoidf_(s[2].x) * tanhf(lc0);
    const float h1_1 = sigmoidf_(s[2].y) * tanhf(lc1);

    float* out_h1 = out;
    float* out_c1 = out + (size_t)BATCH * HD;
    *(float2*)&out_h1[(size_t)b * HD + 2 * t] = make_float2(h1_0, h1_1);
    *(float2*)&out_c1[(size_t)b * HD + 2 * t] = make_float2(c1_0, c1_1);
}

// ---------------------------------------------------------------------------
// Launch
// ---------------------------------------------------------------------------
extern "C" void kernel_launch(void* const* d_in, const int* in_sizes, int n_in,
                              void* d_out, int out_size)
{
    const float* x      = (const float*)d_in[0];
    const float* h0     = (const float*)d_in[1];
    const float* c0     = (const float*)d_in[2];
    const float* w_ih   = (const float*)d_in[3];
    const float* w_hh   = (const float*)d_in[4];
    const float* bias_x = (const float*)d_in[5];
    const float* bias_h = (const float*)d_in[6];
    const float* g_ih   = (const float*)d_in[7];
    const float* b_ih   = (const float*)d_in[8];
    const float* g_hh   = (const float*)d_in[9];
    const float* b_hh   = (const float*)d_in[10];
    const float* g_c    = (const float*)d_in[11];
    const float* b_c    = (const float*)d_in[12];
    float* out = (float*)d_out;

    __half *wi_ptr, *wh_ptr, *x16, *h16, *wih16, *whh16;
    cudaGetSymbolAddress((void**)&wi_ptr, g_wi);
    cudaGetSymbolAddress((void**)&wh_ptr, g_wh);
    cudaGetSymbolAddress((void**)&x16,   g_x16);
    cudaGetSymbolAddress((void**)&h16,   g_h16);
    cudaGetSymbolAddress((void**)&wih16, g_wih16);
    cudaGetSymbolAddress((void**)&whh16, g_whh16);

    cudaFuncSetAttribute(gemm_f16_kernel,
                         cudaFuncAttributeMaxDynamicSharedMemorySize, SMEM_DYN);

    // Fused activation conversions (x, h0) in one launch
    const size_t n4 = (size_t)BATCH * KDIM / 4;
    dim3 cg((unsigned)((n4 + 255) / 256), 2);
    cvt16_dual_kernel<<<cg, 256>>>(x, h0, x16, h16, n4);

    // Fused weight transposes in one launch
    dim3 tb(32, 8);
    dim3 tg(FOURH / 32, KDIM / 32, 2);
    transpose16_dual_kernel<<<tg, tb>>>(w_ih, w_hh, wih16, whh16);

    // Both GEMMs in one launch: z=0 -> wi (x @ w_ih), z=1 -> wh (h0 @ w_hh)
    dim3 gg(FOURH / BN, BATCH / BM, 2);     // (16, 128, 2)
    gemm_f16_kernel<<<gg, 256, SMEM_DYN>>>(x16, h16, wih16, whh16,
                                           wi_ptr, wh_ptr);

    // Epilogue: block-per-row (R12 validated)
    lstm_ln_kernel<<<BATCH, 256>>>(c0, bias_x, bias_h, g_ih, b_ih,
                                   g_hh, b_hh, g_c, b_c, out);
}

// round 16
// speedup vs baseline: 1.2755x; 1.0452x over previous
#include <cuda_runtime.h>
#include <cuda_fp16.h>
#include <cstdint>
#include <math.h>

// ---------------------------------------------------------------------------
// Problem constants
// ---------------------------------------------------------------------------
#define BATCH   16384
#define KDIM    512          // I == H == 512 (GEMM K)
#define FOURH   2048
#define HD      512
#define LN_EPS  1e-5f

// Scratch (device globals: allocation-guard-safe)
__device__ __half g_wi[(size_t)BATCH * FOURH];    // x  @ w_ih  (fp16)
__device__ __half g_wh[(size_t)BATCH * FOURH];    // h0 @ w_hh  (fp16)
__device__ __half g_x16[(size_t)BATCH * KDIM];
__device__ __half g_h16[(size_t)BATCH * KDIM];
__device__ __half g_wih16[(size_t)FOURH * KDIM];  // K-major [4H, K]
__device__ __half g_whh16[(size_t)FOURH * KDIM];

// ---------------------------------------------------------------------------
// Fused fp32 -> fp16 convert for x and h0 (blockIdx.y selects source)
// ---------------------------------------------------------------------------
__global__ void cvt16_dual_kernel(const float* __restrict__ x,
                                  const float* __restrict__ h0,
                                  __half* __restrict__ xd,
                                  __half* __restrict__ hd, size_t n4)
{
    const size_t i = (size_t)blockIdx.x * blockDim.x + threadIdx.x;
    if (i >= n4) return;
    const float* src = blockIdx.y ? h0 : x;
    __half*      dst = blockIdx.y ? hd : xd;
    const float4 v = ((const float4*)src)[i];
    ((__half2*)dst)[i * 2]     = __floats2half2_rn(v.x, v.y);
    ((__half2*)dst)[i * 2 + 1] = __floats2half2_rn(v.z, v.w);
}

// ---------------------------------------------------------------------------
// Fused weight transpose+convert: W[K, 4H] fp32 -> WT[4H, K] fp16
// blockIdx.z selects w_ih / w_hh.
// ---------------------------------------------------------------------------
__global__ void transpose16_dual_kernel(const float* __restrict__ Wih,
                                        const float* __restrict__ Whh,
                                        __half* __restrict__ WTih,
                                        __half* __restrict__ WThh)
{
    __shared__ float t[32][33];
    const float* W  = blockIdx.z ? Whh : Wih;
    __half*      WT = blockIdx.z ? WThh : WTih;
    const int bx = blockIdx.x * 32;   // col in W  (n)
    const int by = blockIdx.y * 32;   // row in W  (k)
    const int tx = threadIdx.x, ty = threadIdx.y;
#pragma unroll
    for (int i = 0; i < 32; i += 8)
        t[ty + i][tx] = W[(size_t)(by + ty + i) * FOURH + bx + tx];
    __syncthreads();
#pragma unroll
    for (int i = 0; i < 32; i += 8)
        WT[(size_t)(bx + ty + i) * KDIM + by + tx] = __float2half_rn(t[tx][ty + i]);
}

// ---------------------------------------------------------------------------
// mma.sync fp16 GEMM (single-pass, f32 accumulate, fp16 output) — validated.
// ---------------------------------------------------------------------------
#define BM      128
#define BN      128
#define BKE     64
#define STAGES  3
#define NKIT    (KDIM / BKE)             // 8
#define TILE_B  (128 * 128)              // 16 KB per operand tile
#define A_OFF   0
#define B_OFF   (TILE_B)
#define STAGE_BYTES (2 * TILE_B)         // 32 KB
#define SMEM_DYN (STAGES * STAGE_BYTES + 1024)   // ~97 KB -> 2 CTAs/SM

__device__ __forceinline__ uint32_t cvta_smem(const void* p) {
    return (uint32_t)__cvta_generic_to_shared(p);
}
__device__ __forceinline__ void cp16(uint32_t dst, const void* src) {
    asm volatile("cp.async.cg.shared.global [%0], [%1], 16;" :: "r"(dst), "l"(src));
}
__device__ __forceinline__ void cp_commit() {
    asm volatile("cp.async.commit_group;" ::: "memory");
}
template <int N>
__device__ __forceinline__ void cp_wait() {
    asm volatile("cp.async.wait_group %0;" :: "n"(N) : "memory");
}
__device__ __forceinline__ void ldsm4(uint32_t& r0, uint32_t& r1,
                                      uint32_t& r2, uint32_t& r3, uint32_t addr) {
    asm volatile("ldmatrix.sync.aligned.m8n8.x4.shared.b16 {%0,%1,%2,%3}, [%4];"
                 : "=r"(r0), "=r"(r1), "=r"(r2), "=r"(r3) : "r"(addr));
}
__device__ __forceinline__ void mma16816(float* d, const uint32_t* a,
                                         const uint32_t* b) {
    asm volatile(
        "mma.sync.aligned.m16n8k16.row.col.f32.f16.f16.f32 "
        "{%0,%1,%2,%3}, {%4,%5,%6,%7}, {%8,%9}, {%0,%1,%2,%3};"
        : "+f"(d[0]), "+f"(d[1]), "+f"(d[2]), "+f"(d[3])
        : "r"(a[0]), "r"(a[1]), "r"(a[2]), "r"(a[3]), "r"(b[0]), "r"(b[1]));
}

__global__ void __launch_bounds__(256, 2)
gemm_f16_kernel(const __half* __restrict__ A0, const __half* __restrict__ A1,
                const __half* __restrict__ B0, const __half* __restrict__ B1,
                __half* __restrict__ C0, __half* __restrict__ C1)
{
    extern __shared__ char dsmem_raw[];

    const int tid = threadIdx.x;
    const int wid = tid >> 5;
    const int lid = tid & 31;

    const __half* A = blockIdx.z ? A1 : A0;
    const __half* B = blockIdx.z ? B1 : B0;
    __half*       C = blockIdx.z ? C1 : C0;

    const int brow = blockIdx.y * BM;
    const int bcol = blockIdx.x * BN;

    uint32_t sbase = cvta_smem(dsmem_raw);
    sbase = (sbase + 127u) & ~127u;

    const int wm = (wid & 1) * 64;
    const int wn = (wid >> 1) * 32;

    const int lq = lid >> 3;
    const int lr = lid & 7;
    const int a_row = lr + ((lq & 1) ? 8 : 0);
    const int a_kbh = lq >> 1;
    const int b_row = lr + ((lq >> 1) ? 8 : 0);
    const int b_kbh = lq & 1;

    float acc[4][4][4];
#pragma unroll
    for (int mt = 0; mt < 4; ++mt)
#pragma unroll
        for (int nt = 0; nt < 4; ++nt)
#pragma unroll
            for (int r = 0; r < 4; ++r) acc[mt][nt][r] = 0.0f;

    auto load_stage = [&](int s, int kc) {
        const int k0 = kc * BKE;
        const uint32_t sb = sbase + s * STAGE_BYTES;
#pragma unroll
        for (int i = 0; i < 4; ++i) {
            const int idx = tid + 256 * i;
            const int row = idx >> 3, ch = idx & 7;
            const uint32_t off = (uint32_t)(row * 128 + ((ch ^ (row & 7)) * 16));
            const size_t ga = (size_t)(brow + row) * KDIM + k0 + ch * 8;
            const size_t gb = (size_t)(bcol + row) * KDIM + k0 + ch * 8;
            cp16(sb + A_OFF + off, A + ga);
            cp16(sb + B_OFF + off, B + gb);
        }
        cp_commit();
    };

    load_stage(0, 0);
    load_stage(1, 1);

#pragma unroll 1
    for (int kc = 0; kc < NKIT; ++kc) {
        const int s = kc % STAGES;
        if (kc + 2 < NKIT) load_stage((kc + 2) % STAGES, kc + 2);
        else               cp_commit();
        cp_wait<2>();
        __syncthreads();

        const uint32_t ab = sbase + s * STAGE_BYTES + A_OFF;
        const uint32_t bb = sbase + s * STAGE_BYTES + B_OFF;

#pragma unroll
        for (int ks = 0; ks < 4; ++ks) {
            uint32_t a[4][4], b[8];
#pragma unroll
            for (int mt = 0; mt < 4; ++mt) {
                const int row = wm + mt * 16 + a_row;
                const int ch  = ks * 2 + a_kbh;
                const uint32_t off =
                    (uint32_t)(row * 128 + ((ch ^ (row & 7)) * 16));
                ldsm4(a[mt][0], a[mt][1], a[mt][2], a[mt][3], ab + off);
            }
#pragma unroll
            for (int np = 0; np < 2; ++np) {
                const int row = wn + np * 16 + b_row;
                const int ch  = ks * 2 + b_kbh;
                const uint32_t off =
                    (uint32_t)(row * 128 + ((ch ^ (row & 7)) * 16));
                ldsm4(b[np*4], b[np*4+1], b[np*4+2], b[np*4+3], bb + off);
            }
#pragma unroll
            for (int mt = 0; mt < 4; ++mt)
#pragma unroll
                for (int nt = 0; nt < 4; ++nt) {
                    const int bi = (nt >> 1) * 4 + (nt & 1) * 2;
                    mma16816(acc[mt][nt], a[mt], &b[bi]);
                }
        }
        __syncthreads();
    }

    const int er = lid >> 2;
    const int ec = (lid & 3) * 2;
#pragma unroll
    for (int mt = 0; mt < 4; ++mt) {
#pragma unroll
        for (int nt = 0; nt < 4; ++nt) {
            const int r0 = brow + wm + mt * 16 + er;
            const int cc = bcol + wn + nt * 8 + ec;
            *(__half2*)&C[(size_t)r0 * FOURH + cc] =
                __floats2half2_rn(acc[mt][nt][0], acc[mt][nt][1]);
            *(__half2*)&C[(size_t)(r0 + 8) * FOURH + cc] =
                __floats2half2_rn(acc[mt][nt][2], acc[mt][nt][3]);
        }
    }
}

// ---------------------------------------------------------------------------
// Fast MUFU-based transcendentals (ex2/rcp approx, ~2^-22 rel err):
//   sigmoid(x) = rcp(1 + ex2(-x*log2e))
//   tanh(x)    = 1 - 2*rcp(ex2(2x*log2e) + 1)
// Saturation: ex2 -> inf => rcp -> 0 (correct limits at both ends).
// ---------------------------------------------------------------------------
#define LOG2E 1.4426950408889634f

__device__ __forceinline__ float ex2_(float x) {
    float y;
    asm("ex2.approx.ftz.f32 %0, %1;" : "=f"(y) : "f"(x));
    return y;
}
__device__ __forceinline__ float rcp_(float x) {
    float y;
    asm("rcp.approx.ftz.f32 %0, %1;" : "=f"(y) : "f"(x));
    return y;
}
__device__ __forceinline__ float sigmoidf_(float v) {
    return rcp_(1.0f + ex2_(-v * LOG2E));
}
__device__ __forceinline__ float tanhf_(float v) {
    return 1.0f - 2.0f * rcp_(ex2_(v * (2.0f * LOG2E)) + 1.0f);
}

// ---------------------------------------------------------------------------
// LSTM epilogue — R12/R15 validated block-per-row structure, with MUFU
// transcendentals replacing software expf/tanhf (measured issue-bound:
// 78.2% issue, 67.5% fma+alu at R15).
// Block = 256 threads handles one row; thread t owns hidden units 2t, 2t+1.
// ---------------------------------------------------------------------------
__global__ __launch_bounds__(256)
void lstm_ln_kernel(const float* __restrict__ c0,
                    const float* __restrict__ bias_x,
                    const float* __restrict__ bias_h,
                    const float* __restrict__ g_ih,
                    const float* __restrict__ b_ih,
                    const float* __restrict__ g_hh,
                    const float* __restrict__ b_hh,
                    const float* __restrict__ g_c,
                    const float* __restrict__ b_c,
                    float* __restrict__ out)
{
    const int b = blockIdx.x;
    const int t = threadIdx.x;
    const int lane = t & 31;
    const int warp = t >> 5;

    const __half2* wh2 = (const __half2*)g_wh + (size_t)b * (FOURH / 2);
    const __half2* wi2 = (const __half2*)g_wi + (size_t)b * (FOURH / 2);

    __shared__ float red[32];

    // r indexes the gate (f=0, i=1, o=2, g=3); pair p = t + 256*r covers
    // elements 2p, 2p+1 = gate r, hidden units 2t, 2t+1.
    float2 vh[4], vi[4];
    float s_h = 0.f, ss_h = 0.f, s_i = 0.f, ss_i = 0.f;
#pragma unroll
    for (int r = 0; r < 4; ++r) {
        const int p = t + 256 * r;
        const int j = p * 2;
        float2 a = __half22float2(wh2[p]);
        float2 c = __half22float2(wi2[p]);
        const float2 bh = *(const float2*)&bias_h[j];
        const float2 bx = *(const float2*)&bias_x[j];
        a.x += bh.x; a.y += bh.y;
        c.x += bx.x; c.y += bx.y;
        vh[r] = a; vi[r] = c;
        s_h += a.x + a.y; ss_h += a.x * a.x + a.y * a.y;
        s_i += c.x + c.y; ss_i += c.x * c.x + c.y * c.y;
    }

#pragma unroll
    for (int off = 16; off > 0; off >>= 1) {
        s_h  += __shfl_xor_sync(0xffffffffu, s_h,  off);
        ss_h += __shfl_xor_sync(0xffffffffu, ss_h, off);
        s_i  += __shfl_xor_sync(0xffffffffu, s_i,  off);
        ss_i += __shfl_xor_sync(0xffffffffu, ss_i, off);
    }
    if (lane == 0) {
        red[warp]      = s_h;
        red[8 + warp]  = ss_h;
        red[16 + warp] = s_i;
        red[24 + warp] = ss_i;
    }
    __syncthreads();
    float S_h = 0.f, SS_h = 0.f, S_i = 0.f, SS_i = 0.f;
#pragma unroll
    for (int w = 0; w < 8; ++w) {
        S_h  += red[w];
        SS_h += red[8 + w];
        S_i  += red[16 + w];
        SS_i += red[24 + w];
    }

    const float inv4h  = 1.0f / (float)FOURH;
    const float mean_h = S_h * inv4h;
    const float var_h  = SS_h * inv4h - mean_h * mean_h;
    const float rstd_h = rsqrtf(var_h + LN_EPS);
    const float mean_i = S_i * inv4h;
    const float var_i  = SS_i * inv4h - mean_i * mean_i;
    const float rstd_i = rsqrtf(var_i + LN_EPS);

    float2 s[4];
#pragma unroll
    for (int r = 0; r < 4; ++r) {
        const int j = (t + 256 * r) * 2;
        const float2 gh = *(const float2*)&g_hh[j];
        const float2 bh = *(const float2*)&b_hh[j];
        const float2 gi = *(const float2*)&g_ih[j];
        const float2 bi = *(const float2*)&b_ih[j];
        s[r].x = (vh[r].x - mean_h) * rstd_h * gh.x + bh.x
               + (vi[r].x - mean_i) * rstd_i * gi.x + bi.x;
        s[r].y = (vh[r].y - mean_h) * rstd_h * gh.y + bh.y
               + (vi[r].y - mean_i) * rstd_i * gi.y + bi.y;
    }

    const float2 c0v = *(const float2*)&c0[(size_t)b * HD + 2 * t];

    // s[0]=f, s[1]=i, s[2]=o, s[3]=g  for hidden units 2t (.x), 2t+1 (.y)
    const float c1_0 = sigmoidf_(s[0].x) * c0v.x + sigmoidf_(s[1].x) * tanhf_(s[3].x);
    const float c1_1 = sigmoidf_(s[0].y) * c0v.y + sigmoidf_(s[1].y) * tanhf_(s[3].y);

    float sc  = c1_0 + c1_1;
    float ssc = c1_0 * c1_0 + c1_1 * c1_1;
#pragma unroll
    for (int off = 16; off > 0; off >>= 1) {
        sc  += __shfl_xor_sync(0xffffffffu, sc,  off);
        ssc += __shfl_xor_sync(0xffffffffu, ssc, off);
    }
    __syncthreads();   // protect red[] reuse
    if (lane == 0) {
        red[warp]     = sc;
        red[8 + warp] = ssc;
    }
    __syncthreads();
    float Sc = 0.f, SSc = 0.f;
#pragma unroll
    for (int w = 0; w < 8; ++w) { Sc += red[w]; SSc += red[8 + w]; }

    const float invh   = 1.0f / (float)HD;
    const float mean_c = Sc * invh;
    const float var_c  = SSc * invh - mean_c * mean_c;
    const float rstd_c = rsqrtf(var_c + LN_EPS);

    const float2 gc = *(const float2*)&g_c[2 * t];
    const float2 bc = *(const float2*)&b_c[2 * t];
    const float lc0 = (c1_0 - mean_c) * rstd_c * gc.x + bc.x;
    const float lc1 = (c1_1 - mean_c) * rstd_c * gc.y + bc.y;

    const float h1_0 = sigmoidf_(s[2].x) * tanhf_(lc0);
    const float h1_1 = sigmoidf_(s[2].y) * tanhf_(lc1);

    float* out_h1 = out;
    float* out_c1 = out + (size_t)BATCH * HD;
    *(float2*)&out_h1[(size_t)b * HD + 2 * t] = make_float2(h1_0, h1_1);
    *(float2*)&out_c1[(size_t)b * HD + 2 * t] = make_float2(c1_0, c1_1);
}

// ---------------------------------------------------------------------------
// Launch
// ---------------------------------------------------------------------------
extern "C" void kernel_launch(void* const* d_in, const int* in_sizes, int n_in,
                              void* d_out, int out_size)
{
    const float* x      = (const float*)d_in[0];
    const float* h0     = (const float*)d_in[1];
    const float* c0     = (const float*)d_in[2];
    const float* w_ih   = (const float*)d_in[3];
    const float* w_hh   = (const float*)d_in[4];
    const float* bias_x = (const float*)d_in[5];
    const float* bias_h = (const float*)d_in[6];
    const float* g_ih   = (const float*)d_in[7];
    const float* b_ih   = (const float*)d_in[8];
    const float* g_hh   = (const float*)d_in[9];
    const float* b_hh   = (const float*)d_in[10];
    const float* g_c    = (const float*)d_in[11];
    const float* b_c    = (const float*)d_in[12];
    float* out = (float*)d_out;

    __half *wi_ptr, *wh_ptr, *x16, *h16, *wih16, *whh16;
    cudaGetSymbolAddress((void**)&wi_ptr, g_wi);
    cudaGetSymbolAddress((void**)&wh_ptr, g_wh);
    cudaGetSymbolAddress((void**)&x16,   g_x16);
    cudaGetSymbolAddress((void**)&h16,   g_h16);
    cudaGetSymbolAddress((void**)&wih16, g_wih16);
    cudaGetSymbolAddress((void**)&whh16, g_whh16);

    cudaFuncSetAttribute(gemm_f16_kernel,
                         cudaFuncAttributeMaxDynamicSharedMemorySize, SMEM_DYN);

    // Fused activation conversions (x, h0) in one launch
    const size_t n4 = (size_t)BATCH * KDIM / 4;
    dim3 cg((unsigned)((n4 + 255) / 256), 2);
    cvt16_dual_kernel<<<cg, 256>>>(x, h0, x16, h16, n4);

    // Fused weight transposes in one launch
    dim3 tb(32, 8);
    dim3 tg(FOURH / 32, KDIM / 32, 2);
    transpose16_dual_kernel<<<tg, tb>>>(w_ih, w_hh, wih16, whh16);

    // Both GEMMs in one launch: z=0 -> wi (x @ w_ih), z=1 -> wh (h0 @ w_hh)
    dim3 gg(FOURH / BN, BATCH / BM, 2);     // (16, 128, 2)
    gemm_f16_kernel<<<gg, 256, SMEM_DYN>>>(x16, h16, wih16, whh16,
                                           wi_ptr, wh_ptr);

    // Epilogue: block-per-row (validated) with MUFU transcendentals
    lstm_ln_kernel<<<BATCH, 256>>>(c0, bias_x, bias_h, g_ih, b_ih,
                                   g_hh, b_hh, g_c, b_c, out);
}

// round 17
// speedup vs baseline: 1.2829x; 1.0058x over previous
#include <cuda_runtime.h>
#include <cuda_fp16.h>
#include <cstdint>
#include <math.h>

// ---------------------------------------------------------------------------
// Problem constants
// ---------------------------------------------------------------------------
#define BATCH   16384
#define KDIM    512          // I == H == 512 (GEMM K)
#define FOURH   2048
#define HD      512
#define LN_EPS  1e-5f

// Scratch (device globals: allocation-guard-safe)
__device__ __half g_wi[(size_t)BATCH * FOURH];    // x  @ w_ih  (fp16)
__device__ __half g_wh[(size_t)BATCH * FOURH];    // h0 @ w_hh  (fp16)
__device__ __half g_x16[(size_t)BATCH * KDIM];
__device__ __half g_h16[(size_t)BATCH * KDIM];
__device__ __half g_wih16[(size_t)FOURH * KDIM];  // K-major [4H, K]
__device__ __half g_whh16[(size_t)FOURH * KDIM];
// Packed fp16 LN parameters (built once per call by pack_params_kernel)
__device__ uint2 g_pb[FOURH / 2];   // {bias_h2, bias_x2} per half2-pair
__device__ uint4 g_pg[FOURH / 2];   // {g_hh2, b_hh2, g_ih2, b_ih2}
__device__ uint2 g_pc[HD / 2];      // {g_c2, b_c2}

// ---------------------------------------------------------------------------
// Helpers: float2 <-> packed half2 (as uint32)
// ---------------------------------------------------------------------------
__device__ __forceinline__ uint32_t f2h2(float a, float b) {
    __half2 h = __floats2half2_rn(a, b);
    return *reinterpret_cast<uint32_t*>(&h);
}
__device__ __forceinline__ float2 h2f(uint32_t h) {
    return __half22float2(*reinterpret_cast<__half2*>(&h));
}

// ---------------------------------------------------------------------------
// Pack LN params to fp16 (one tiny launch; 1024 pairs + 256 pairs)
// ---------------------------------------------------------------------------
__global__ void pack_params_kernel(const float* __restrict__ bias_x,
                                   const float* __restrict__ bias_h,
                                   const float* __restrict__ g_ih,
                                   const float* __restrict__ b_ih,
                                   const float* __restrict__ g_hh,
                                   const float* __restrict__ b_hh,
                                   const float* __restrict__ g_c,
                                   const float* __restrict__ b_c)
{
    const int p = blockIdx.x * blockDim.x + threadIdx.x;
    if (p < FOURH / 2) {
        const int j = 2 * p;
        g_pb[p] = make_uint2(f2h2(bias_h[j], bias_h[j + 1]),
                             f2h2(bias_x[j], bias_x[j + 1]));
        g_pg[p] = make_uint4(f2h2(g_hh[j], g_hh[j + 1]),
                             f2h2(b_hh[j], b_hh[j + 1]),
                             f2h2(g_ih[j], g_ih[j + 1]),
                             f2h2(b_ih[j], b_ih[j + 1]));
    }
    if (p < HD / 2) {
        const int j = 2 * p;
        g_pc[p] = make_uint2(f2h2(g_c[j], g_c[j + 1]),
                             f2h2(b_c[j], b_c[j + 1]));
    }
}

// ---------------------------------------------------------------------------
// Fused fp32 -> fp16 convert for x and h0 (blockIdx.y selects source)
// ---------------------------------------------------------------------------
__global__ void cvt16_dual_kernel(const float* __restrict__ x,
                                  const float* __restrict__ h0,
                                  __half* __restrict__ xd,
                                  __half* __restrict__ hd, size_t n4)
{
    const size_t i = (size_t)blockIdx.x * blockDim.x + threadIdx.x;
    if (i >= n4) return;
    const float* src = blockIdx.y ? h0 : x;
    __half*      dst = blockIdx.y ? hd : xd;
    const float4 v = ((const float4*)src)[i];
    ((__half2*)dst)[i * 2]     = __floats2half2_rn(v.x, v.y);
    ((__half2*)dst)[i * 2 + 1] = __floats2half2_rn(v.z, v.w);
}

// ---------------------------------------------------------------------------
// Fused weight transpose+convert: W[K, 4H] fp32 -> WT[4H, K] fp16
// ---------------------------------------------------------------------------
__global__ void transpose16_dual_kernel(const float* __restrict__ Wih,
                                        const float* __restrict__ Whh,
                                        __half* __restrict__ WTih,
                                        __half* __restrict__ WThh)
{
    __shared__ float t[32][33];
    const float* W  = blockIdx.z ? Whh : Wih;
    __half*      WT = blockIdx.z ? WThh : WTih;
    const int bx = blockIdx.x * 32;
    const int by = blockIdx.y * 32;
    const int tx = threadIdx.x, ty = threadIdx.y;
#pragma unroll
    for (int i = 0; i < 32; i += 8)
        t[ty + i][tx] = W[(size_t)(by + ty + i) * FOURH + bx + tx];
    __syncthreads();
#pragma unroll
    for (int i = 0; i < 32; i += 8)
        WT[(size_t)(bx + ty + i) * KDIM + by + tx] = __float2half_rn(t[tx][ty + i]);
}

// ---------------------------------------------------------------------------
// mma.sync fp16 GEMM (single-pass, f32 accumulate, fp16 output) — validated.
// ---------------------------------------------------------------------------
#define BM      128
#define BN      128
#define BKE     64
#define STAGES  3
#define NKIT    (KDIM / BKE)             // 8
#define TILE_B  (128 * 128)
#define A_OFF   0
#define B_OFF   (TILE_B)
#define STAGE_BYTES (2 * TILE_B)         // 32 KB
#define SMEM_DYN (STAGES * STAGE_BYTES + 1024)   // ~97 KB -> 2 CTAs/SM

__device__ __forceinline__ uint32_t cvta_smem(const void* p) {
    return (uint32_t)__cvta_generic_to_shared(p);
}
__device__ __forceinline__ void cp16(uint32_t dst, const void* src) {
    asm volatile("cp.async.cg.shared.global [%0], [%1], 16;" :: "r"(dst), "l"(src));
}
__device__ __forceinline__ void cp_commit() {
    asm volatile("cp.async.commit_group;" ::: "memory");
}
template <int N>
__device__ __forceinline__ void cp_wait() {
    asm volatile("cp.async.wait_group %0;" :: "n"(N) : "memory");
}
__device__ __forceinline__ void ldsm4(uint32_t& r0, uint32_t& r1,
                                      uint32_t& r2, uint32_t& r3, uint32_t addr) {
    asm volatile("ldmatrix.sync.aligned.m8n8.x4.shared.b16 {%0,%1,%2,%3}, [%4];"
                 : "=r"(r0), "=r"(r1), "=r"(r2), "=r"(r3) : "r"(addr));
}
__device__ __forceinline__ void mma16816(float* d, const uint32_t* a,
                                         const uint32_t* b) {
    asm volatile(
        "mma.sync.aligned.m16n8k16.row.col.f32.f16.f16.f32 "
        "{%0,%1,%2,%3}, {%4,%5,%6,%7}, {%8,%9}, {%0,%1,%2,%3};"
        : "+f"(d[0]), "+f"(d[1]), "+f"(d[2]), "+f"(d[3])
        : "r"(a[0]), "r"(a[1]), "r"(a[2]), "r"(a[3]), "r"(b[0]), "r"(b[1]));
}

__global__ void __launch_bounds__(256, 2)
gemm_f16_kernel(const __half* __restrict__ A0, const __half* __restrict__ A1,
                const __half* __restrict__ B0, const __half* __restrict__ B1,
                __half* __restrict__ C0, __half* __restrict__ C1)
{
    extern __shared__ char dsmem_raw[];

    const int tid = threadIdx.x;
    const int wid = tid >> 5;
    const int lid = tid & 31;

    const __half* A = blockIdx.z ? A1 : A0;
    const __half* B = blockIdx.z ? B1 : B0;
    __half*       C = blockIdx.z ? C1 : C0;

    const int brow = blockIdx.y * BM;
    const int bcol = blockIdx.x * BN;

    uint32_t sbase = cvta_smem(dsmem_raw);
    sbase = (sbase + 127u) & ~127u;

    const int wm = (wid & 1) * 64;
    const int wn = (wid >> 1) * 32;

    const int lq = lid >> 3;
    const int lr = lid & 7;
    const int a_row = lr + ((lq & 1) ? 8 : 0);
    const int a_kbh = lq >> 1;
    const int b_row = lr + ((lq >> 1) ? 8 : 0);
    const int b_kbh = lq & 1;

    float acc[4][4][4];
#pragma unroll
    for (int mt = 0; mt < 4; ++mt)
#pragma unroll
        for (int nt = 0; nt < 4; ++nt)
#pragma unroll
            for (int r = 0; r < 4; ++r) acc[mt][nt][r] = 0.0f;

    auto load_stage = [&](int s, int kc) {
        const int k0 = kc * BKE;
        const uint32_t sb = sbase + s * STAGE_BYTES;
#pragma unroll
        for (int i = 0; i < 4; ++i) {
            const int idx = tid + 256 * i;
            const int row = idx >> 3, ch = idx & 7;
            const uint32_t off = (uint32_t)(row * 128 + ((ch ^ (row & 7)) * 16));
            const size_t ga = (size_t)(brow + row) * KDIM + k0 + ch * 8;
            const size_t gb = (size_t)(bcol + row) * KDIM + k0 + ch * 8;
            cp16(sb + A_OFF + off, A + ga);
            cp16(sb + B_OFF + off, B + gb);
        }
        cp_commit();
    };

    load_stage(0, 0);
    load_stage(1, 1);

#pragma unroll 1
    for (int kc = 0; kc < NKIT; ++kc) {
        const int s = kc % STAGES;
        if (kc + 2 < NKIT) load_stage((kc + 2) % STAGES, kc + 2);
        else               cp_commit();
        cp_wait<2>();
        __syncthreads();

        const uint32_t ab = sbase + s * STAGE_BYTES + A_OFF;
        const uint32_t bb = sbase + s * STAGE_BYTES + B_OFF;

#pragma unroll
        for (int ks = 0; ks < 4; ++ks) {
            uint32_t a[4][4], b[8];
#pragma unroll
            for (int mt = 0; mt < 4; ++mt) {
                const int row = wm + mt * 16 + a_row;
                const int ch  = ks * 2 + a_kbh;
                const uint32_t off =
                    (uint32_t)(row * 128 + ((ch ^ (row & 7)) * 16));
                ldsm4(a[mt][0], a[mt][1], a[mt][2], a[mt][3], ab + off);
            }
#pragma unroll
            for (int np = 0; np < 2; ++np) {
                const int row = wn + np * 16 + b_row;
                const int ch  = ks * 2 + b_kbh;
                const uint32_t off =
                    (uint32_t)(row * 128 + ((ch ^ (row & 7)) * 16));
                ldsm4(b[np*4], b[np*4+1], b[np*4+2], b[np*4+3], bb + off);
            }
#pragma unroll
            for (int mt = 0; mt < 4; ++mt)
#pragma unroll
                for (int nt = 0; nt < 4; ++nt) {
                    const int bi = (nt >> 1) * 4 + (nt & 1) * 2;
                    mma16816(acc[mt][nt], a[mt], &b[bi]);
                }
        }
        __syncthreads();
    }

    const int er = lid >> 2;
    const int ec = (lid & 3) * 2;
#pragma unroll
    for (int mt = 0; mt < 4; ++mt) {
#pragma unroll
        for (int nt = 0; nt < 4; ++nt) {
            const int r0 = brow + wm + mt * 16 + er;
            const int cc = bcol + wn + nt * 8 + ec;
            *(__half2*)&C[(size_t)r0 * FOURH + cc] =
                __floats2half2_rn(acc[mt][nt][0], acc[mt][nt][1]);
            *(__half2*)&C[(size_t)(r0 + 8) * FOURH + cc] =
                __floats2half2_rn(acc[mt][nt][2], acc[mt][nt][3]);
        }
    }
}

// ---------------------------------------------------------------------------
// Fast MUFU transcendentals (validated R16: ~2^-22 rel err, correct limits)
// ---------------------------------------------------------------------------
#define LOG2E 1.4426950408889634f

__device__ __forceinline__ float ex2_(float x) {
    float y;
    asm("ex2.approx.ftz.f32 %0, %1;" : "=f"(y) : "f"(x));
    return y;
}
__device__ __forceinline__ float rcp_(float x) {
    float y;
    asm("rcp.approx.ftz.f32 %0, %1;" : "=f"(y) : "f"(x));
    return y;
}
__device__ __forceinline__ float sigmoidf_(float v) {
    return rcp_(1.0f + ex2_(-v * LOG2E));
}
__device__ __forceinline__ float tanhf_(float v) {
    return 1.0f - 2.0f * rcp_(ex2_(v * (2.0f * LOG2E)) + 1.0f);
}

// ---------------------------------------------------------------------------
// LSTM epilogue — validated block-per-row structure + MUFU transcendentals,
// now with fp16-packed LN params (R16 profile: L1tex 79.4% binding; param
// bytes/thread 208 -> 104, param load instructions ~14 -> ~6).
// ---------------------------------------------------------------------------
__global__ __launch_bounds__(256)
void lstm_ln_kernel(const float* __restrict__ c0, float* __restrict__ out)
{
    const int b = blockIdx.x;
    const int t = threadIdx.x;
    const int lane = t & 31;
    const int warp = t >> 5;

    const __half2* wh2 = (const __half2*)g_wh + (size_t)b * (FOURH / 2);
    const __half2* wi2 = (const __half2*)g_wi + (size_t)b * (FOURH / 2);

    __shared__ float red[32];

    // r indexes the gate (f=0, i=1, o=2, g=3); pair p = t + 256*r covers
    // elements 2p, 2p+1 = gate r, hidden units 2t, 2t+1.
    float2 vh[4], vi[4];
    float s_h = 0.f, ss_h = 0.f, s_i = 0.f, ss_i = 0.f;
#pragma unroll
    for (int r = 0; r < 4; ++r) {
        const int p = t + 256 * r;
        float2 a = __half22float2(wh2[p]);
        float2 c = __half22float2(wi2[p]);
        const uint2 pb = g_pb[p];
        const float2 bh = h2f(pb.x);
        const float2 bx = h2f(pb.y);
        a.x += bh.x; a.y += bh.y;
        c.x += bx.x; c.y += bx.y;
        vh[r] = a; vi[r] = c;
        s_h += a.x + a.y; ss_h += a.x * a.x + a.y * a.y;
        s_i += c.x + c.y; ss_i += c.x * c.x + c.y * c.y;
    }

#pragma unroll
    for (int off = 16; off > 0; off >>= 1) {
        s_h  += __shfl_xor_sync(0xffffffffu, s_h,  off);
        ss_h += __shfl_xor_sync(0xffffffffu, ss_h, off);
        s_i  += __shfl_xor_sync(0xffffffffu, s_i,  off);
        ss_i += __shfl_xor_sync(0xffffffffu, ss_i, off);
    }
    if (lane == 0) {
        red[warp]      = s_h;
        red[8 + warp]  = ss_h;
        red[16 + warp] = s_i;
        red[24 + warp] = ss_i;
    }
    __syncthreads();
    float S_h = 0.f, SS_h = 0.f, S_i = 0.f, SS_i = 0.f;
#pragma unroll
    for (int w = 0; w < 8; ++w) {
        S_h  += red[w];
        SS_h += red[8 + w];
        S_i  += red[16 + w];
        SS_i += red[24 + w];
    }

    const float inv4h  = 1.0f / (float)FOURH;
    const float mean_h = S_h * inv4h;
    const float var_h  = SS_h * inv4h - mean_h * mean_h;
    const float rstd_h = rsqrtf(var_h + LN_EPS);
    const float mean_i = S_i * inv4h;
    const float var_i  = SS_i * inv4h - mean_i * mean_i;
    const float rstd_i = rsqrtf(var_i + LN_EPS);

    float2 s[4];
#pragma unroll
    for (int r = 0; r < 4; ++r) {
        const int p = t + 256 * r;
        const uint4 pg = g_pg[p];
        const float2 gh = h2f(pg.x);
        const float2 bh = h2f(pg.y);
        const float2 gi = h2f(pg.z);
        const float2 bi = h2f(pg.w);
        s[r].x = (vh[r].x - mean_h) * rstd_h * gh.x + bh.x
               + (vi[r].x - mean_i) * rstd_i * gi.x + bi.x;
        s[r].y = (vh[r].y - mean_h) * rstd_h * gh.y + bh.y
               + (vi[r].y - mean_i) * rstd_i * gi.y + bi.y;
    }

    const float2 c0v = *(const float2*)&c0[(size_t)b * HD + 2 * t];

    // s[0]=f, s[1]=i, s[2]=o, s[3]=g  for hidden units 2t (.x), 2t+1 (.y)
    const float c1_0 = sigmoidf_(s[0].x) * c0v.x + sigmoidf_(s[1].x) * tanhf_(s[3].x);
    const float c1_1 = sigmoidf_(s[0].y) * c0v.y + sigmoidf_(s[1].y) * tanhf_(s[3].y);

    float sc  = c1_0 + c1_1;
    float ssc = c1_0 * c1_0 + c1_1 * c1_1;
#pragma unroll
    for (int off = 16; off > 0; off >>= 1) {
        sc  += __shfl_xor_sync(0xffffffffu, sc,  off);
        ssc += __shfl_xor_sync(0xffffffffu, ssc, off);
    }
    __syncthreads();   // protect red[] reuse
    if (lane == 0) {
        red[warp]     = sc;
        red[8 + warp] = ssc;
    }
    __syncthreads();
    float Sc = 0.f, SSc = 0.f;
#pragma unroll
    for (int w = 0; w < 8; ++w) { Sc += red[w]; SSc += red[8 + w]; }

    const float invh   = 1.0f / (float)HD;
    const float mean_c = Sc * invh;
    const float var_c  = SSc * invh - mean_c * mean_c;
    const float rstd_c = rsqrtf(var_c + LN_EPS);

    const uint2 pc = g_pc[t];
    const float2 gc = h2f(pc.x);
    const float2 bc = h2f(pc.y);
    const float lc0 = (c1_0 - mean_c) * rstd_c * gc.x + bc.x;
    const float lc1 = (c1_1 - mean_c) * rstd_c * gc.y + bc.y;

    const float h1_0 = sigmoidf_(s[2].x) * tanhf_(lc0);
    const float h1_1 = sigmoidf_(s[2].y) * tanhf_(lc1);

    float* out_h1 = out;
    float* out_c1 = out + (size_t)BATCH * HD;
    *(float2*)&out_h1[(size_t)b * HD + 2 * t] = make_float2(h1_0, h1_1);
    *(float2*)&out_c1[(size_t)b * HD + 2 * t] = make_float2(c1_0, c1_1);
}

// ---------------------------------------------------------------------------
// Launch
// ---------------------------------------------------------------------------
extern "C" void kernel_launch(void* const* d_in, const int* in_sizes, int n_in,
                              void* d_out, int out_size)
{
    const float* x      = (const float*)d_in[0];
    const float* h0     = (const float*)d_in[1];
    const float* c0     = (const float*)d_in[2];
    const float* w_ih   = (const float*)d_in[3];
    const float* w_hh   = (const float*)d_in[4];
    const float* bias_x = (const float*)d_in[5];
    const float* bias_h = (const float*)d_in[6];
    const float* g_ih   = (const float*)d_in[7];
    const float* b_ih   = (const float*)d_in[8];
    const float* g_hh   = (const float*)d_in[9];
    const float* b_hh   = (const float*)d_in[10];
    const float* g_c    = (const float*)d_in[11];
    const float* b_c    = (const float*)d_in[12];
    float* out = (float*)d_out;

    __half *wi_ptr, *wh_ptr, *x16, *h16, *wih16, *whh16;
    cudaGetSymbolAddress((void**)&wi_ptr, g_wi);
    cudaGetSymbolAddress((void**)&wh_ptr, g_wh);
    cudaGetSymbolAddress((void**)&x16,   g_x16);
    cudaGetSymbolAddress((void**)&h16,   g_h16);
    cudaGetSymbolAddress((void**)&wih16, g_wih16);
    cudaGetSymbolAddress((void**)&whh16, g_whh16);

    cudaFuncSetAttribute(gemm_f16_kernel,
                         cudaFuncAttributeMaxDynamicSharedMemorySize, SMEM_DYN);

    // Pack LN params (fp16) — tiny
    pack_params_kernel<<<4, 256>>>(bias_x, bias_h, g_ih, b_ih,
                                   g_hh, b_hh, g_c, b_c);

    // Fused activation conversions (x, h0) in one launch
    const size_t n4 = (size_t)BATCH * KDIM / 4;
    dim3 cg((unsigned)((n4 + 255) / 256), 2);
    cvt16_dual_kernel<<<cg, 256>>>(x, h0, x16, h16, n4);

    // Fused weight transposes in one launch
    dim3 tb(32, 8);
    dim3 tg(FOURH / 32, KDIM / 32, 2);
    transpose16_dual_kernel<<<tg, tb>>>(w_ih, w_hh, wih16, whh16);

    // Both GEMMs in one launch: z=0 -> wi (x @ w_ih), z=1 -> wh (h0 @ w_hh)
    dim3 gg(FOURH / BN, BATCH / BM, 2);     // (16, 128, 2)
    gemm_f16_kernel<<<gg, 256, SMEM_DYN>>>(x16, h16, wih16, whh16,
                                           wi_ptr, wh_ptr);

    // Epilogue: block-per-row, MUFU transcendentals, packed fp16 params
    lstm_ln_kernel<<<BATCH, 256>>>(c0, out);
}